// round 1
// baseline (speedup 1.0000x reference)
#include <cuda_runtime.h>
#include <math.h>
#include <float.h>

// Problem constants
#define BATCH   4
#define TSEQ    1024
#define DMODEL  1024
#define NHEAD   16
#define HDIM    64
#define NLAYER  4
#define VOCAB   32000
#define NTOK    (BATCH*TSEQ)        // 4096 rows
#define FFDIM   (4*DMODEL)          // 4096

// ---------------- scratch (device globals; no allocation allowed) ----------
__device__ float g_h  [(size_t)NTOK*DMODEL];
__device__ float g_xn [(size_t)NTOK*DMODEL];
__device__ float g_q  [(size_t)NTOK*DMODEL];
__device__ float g_k  [(size_t)NTOK*DMODEL];
__device__ float g_v  [(size_t)NTOK*DMODEL];
__device__ float g_y  [(size_t)NTOK*DMODEL];
__device__ float g_ff [(size_t)NTOK*FFDIM];
__device__ float g_sc [(size_t)BATCH*NHEAD*TSEQ*TSEQ];
__device__ float g_wq [(size_t)DMODEL*DMODEL];
__device__ float g_wk [(size_t)DMODEL*DMODEL];
__device__ float g_wv [(size_t)DMODEL*DMODEL];

// ---------------- block reduce helper (blockDim = 256) ---------------------
template<bool DOMAX>
__device__ __forceinline__ float block_reduce(float x) {
    #pragma unroll
    for (int o = 16; o; o >>= 1) {
        float t = __shfl_xor_sync(0xFFFFFFFFu, x, o);
        x = DOMAX ? fmaxf(x, t) : x + t;
    }
    __shared__ float sh[8];
    int w = threadIdx.x >> 5;
    __syncthreads();                       // protect reuse of sh
    if ((threadIdx.x & 31) == 0) sh[w] = x;
    __syncthreads();
    float r = sh[0];
    #pragma unroll
    for (int i = 1; i < 8; i++) r = DOMAX ? fmaxf(r, sh[i]) : r + sh[i];
    return r;
}

// ---------------- weight repack:  Wr[d][h*64+k] = W[h][d][k] ----------------
__global__ __launch_bounds__(256) void repack_kernel(const float* __restrict__ W,
                                                     float* __restrict__ Wr) {
    int idx = blockIdx.x * 256 + threadIdx.x;      // over 1M
    int d = idx >> 10, col = idx & 1023;
    int h = col >> 6,  kk  = col & 63;
    Wr[idx] = W[((size_t)h * DMODEL + d) * HDIM + kk];
}

// ---------------- embedding ------------------------------------------------
__global__ __launch_bounds__(256) void embed_kernel(const int* __restrict__ x,
                                                    const float* __restrict__ tok,
                                                    const float* __restrict__ pos,
                                                    float* __restrict__ H) {
    int row = blockIdx.x;                 // 0..4095 = b*T+t
    int tid = row % TSEQ;
    size_t tb = (size_t)x[row] * DMODEL;
    size_t pb = (size_t)tid * DMODEL;
    size_t hb = (size_t)row * DMODEL;
    #pragma unroll
    for (int i = 0; i < 4; i++) {
        int c = threadIdx.x + i * 256;
        H[hb + c] = tok[tb + c] + pos[pb + c];
    }
}

// ---------------- layernorm ------------------------------------------------
__global__ __launch_bounds__(256) void ln_kernel(const float* __restrict__ X,
                                                 const float* __restrict__ g,
                                                 const float* __restrict__ b,
                                                 float* __restrict__ O) {
    size_t base = (size_t)blockIdx.x * DMODEL;
    float v[4], s = 0.f, sq = 0.f;
    #pragma unroll
    for (int i = 0; i < 4; i++) {
        v[i] = X[base + threadIdx.x + i * 256];
        s += v[i]; sq += v[i] * v[i];
    }
    s  = block_reduce<false>(s);
    sq = block_reduce<false>(sq);
    float mu  = s  * (1.f / DMODEL);
    float var = sq * (1.f / DMODEL) - mu * mu;
    float rstd = rsqrtf(var + 1e-5f);
    #pragma unroll
    for (int i = 0; i < 4; i++) {
        int c = threadIdx.x + i * 256;
        O[base + c] = (v[i] - mu) * rstd * g[c] + b[c];
    }
}

// ---------------- generic SGEMM: C[M,N] = A[M,K] @ B[K,N] + bias  ----------
// MODE 0: store ; MODE 1: relu ; MODE 2: C += (residual, C preloaded)
// requires M%128==0, N%128==0, K%16==0
template<int MODE>
__global__ __launch_bounds__(256) void sgemm_kernel(const float* __restrict__ A,
                                                    const float* __restrict__ B,
                                                    const float* __restrict__ bias,
                                                    float* __restrict__ C,
                                                    int M, int N, int K) {
    __shared__ float As[16][132];   // [k][m] transposed, padded
    __shared__ float Bs[16][128];   // [k][n]
    int tid = threadIdx.x;
    int bm = blockIdx.y * 128, bn = blockIdx.x * 128;
    int tr = tid >> 4, tc = tid & 15;
    float acc[8][8] = {};
    for (int k0 = 0; k0 < K; k0 += 16) {
        #pragma unroll
        for (int i = 0; i < 2; i++) {
            int idx = tid + i * 256;                // 0..511
            int ar = idx >> 2, ac = (idx & 3) * 4;  // A: 128 rows x 16 k
            float4 av = *(const float4*)&A[(size_t)(bm + ar) * K + k0 + ac];
            As[ac + 0][ar] = av.x; As[ac + 1][ar] = av.y;
            As[ac + 2][ar] = av.z; As[ac + 3][ar] = av.w;
            int br = idx >> 5, bc = (idx & 31) * 4; // B: 16 k x 128 cols
            *(float4*)&Bs[br][bc] = *(const float4*)&B[(size_t)(k0 + br) * N + bn + bc];
        }
        __syncthreads();
        #pragma unroll
        for (int k = 0; k < 16; k++) {
            float ra[8], rb[8];
            #pragma unroll
            for (int i = 0; i < 8; i++) ra[i] = As[k][tr * 8 + i];
            #pragma unroll
            for (int j = 0; j < 8; j++) rb[j] = Bs[k][tc * 8 + j];
            #pragma unroll
            for (int i = 0; i < 8; i++)
                #pragma unroll
                for (int j = 0; j < 8; j++)
                    acc[i][j] += ra[i] * rb[j];
        }
        __syncthreads();
    }
    #pragma unroll
    for (int i = 0; i < 8; i++) {
        size_t m = bm + tr * 8 + i;
        #pragma unroll
        for (int jj = 0; jj < 2; jj++) {
            int n = bn + tc * 8 + jj * 4;
            float4 bv = *(const float4*)&bias[n];
            float4 o;
            o.x = acc[i][jj*4+0] + bv.x; o.y = acc[i][jj*4+1] + bv.y;
            o.z = acc[i][jj*4+2] + bv.z; o.w = acc[i][jj*4+3] + bv.w;
            if (MODE == 1) {
                o.x = fmaxf(o.x, 0.f); o.y = fmaxf(o.y, 0.f);
                o.z = fmaxf(o.z, 0.f); o.w = fmaxf(o.w, 0.f);
            }
            float* cp = &C[m * (size_t)N + n];
            if (MODE == 2) {
                float4 r = *(float4*)cp;
                o.x += r.x; o.y += r.y; o.z += r.z; o.w += r.w;
            }
            *(float4*)cp = o;
        }
    }
}

// ---------------- scores: S[bh,t,s] = scale * q[b,h,t,:]·k[b,h,s,:] --------
__global__ __launch_bounds__(256) void scores_kernel(const float* __restrict__ Q,
                                                     const float* __restrict__ Kv,
                                                     float* __restrict__ S) {
    int t0 = blockIdx.y * 32, s0 = blockIdx.x * 32;
    if (s0 > t0 + 31) return;                        // fully masked tile
    int bh = blockIdx.z;
    int b = bh >> 4, h = bh & 15;
    __shared__ float Qs[64][33];                     // [k][t]
    __shared__ float Ks[64][33];                     // [k][s]
    int tid = threadIdx.x;
    #pragma unroll
    for (int i = 0; i < 2; i++) {
        int idx = tid + i * 256;                     // 0..511
        int r = idx >> 4, c = (idx & 15) * 4;        // 32 rows x 64 k
        float4 qv = *(const float4*)&Q[((size_t)(b * TSEQ + t0 + r)) * DMODEL + h * HDIM + c];
        Qs[c+0][r] = qv.x; Qs[c+1][r] = qv.y; Qs[c+2][r] = qv.z; Qs[c+3][r] = qv.w;
        float4 kv = *(const float4*)&Kv[((size_t)(b * TSEQ + s0 + r)) * DMODEL + h * HDIM + c];
        Ks[c+0][r] = kv.x; Ks[c+1][r] = kv.y; Ks[c+2][r] = kv.z; Ks[c+3][r] = kv.w;
    }
    __syncthreads();
    int tr = tid >> 4, tc = tid & 15;
    float a00 = 0.f, a01 = 0.f, a10 = 0.f, a11 = 0.f;
    #pragma unroll
    for (int k = 0; k < 64; k++) {
        float q0 = Qs[k][tr*2], q1 = Qs[k][tr*2+1];
        float k0 = Ks[k][tc*2], k1 = Ks[k][tc*2+1];
        a00 += q0 * k0; a01 += q0 * k1; a10 += q1 * k0; a11 += q1 * k1;
    }
    const float scale = 0.125f;                       // 1/sqrt(64)
    size_t rb0 = ((size_t)bh * TSEQ + t0 + tr*2) * TSEQ + s0 + tc*2;
    size_t rb1 = rb0 + TSEQ;
    S[rb0]   = a00 * scale; S[rb0+1] = a01 * scale;
    S[rb1]   = a10 * scale; S[rb1+1] = a11 * scale;
}

// ---------------- masked softmax (in place); row = bh*T + t ----------------
__global__ __launch_bounds__(256) void softmax_kernel(float* __restrict__ S) {
    int row = blockIdx.x;
    int t = row & (TSEQ - 1);
    float* sr = S + (size_t)row * TSEQ;
    float v[4], mx = -FLT_MAX;
    #pragma unroll
    for (int i = 0; i < 4; i++) {
        int s = threadIdx.x + i * 256;
        float val = sr[s];
        // source quirk: tril, then (==0) -> -inf  (causal OR exact-zero mask)
        if (s > t || val == 0.0f) val = -FLT_MAX;
        v[i] = val; mx = fmaxf(mx, val);
    }
    float M = block_reduce<true>(mx);
    float sum = 0.f;
    #pragma unroll
    for (int i = 0; i < 4; i++) {
        float e = (v[i] == -FLT_MAX) ? 0.f : expf(v[i] - M);
        v[i] = e; sum += e;
    }
    sum = block_reduce<false>(sum);
    float inv = 1.f / sum;
    #pragma unroll
    for (int i = 0; i < 4; i++)
        sr[threadIdx.x + i * 256] = v[i] * inv;
}

// ---------------- y = P @ V  (per b,h; exploit causal truncation) ----------
__global__ __launch_bounds__(256) void av_kernel(const float* __restrict__ S,
                                                 const float* __restrict__ Vv,
                                                 float* __restrict__ Y) {
    int bh = blockIdx.y;
    int b = bh >> 4, h = bh & 15;
    int t0 = blockIdx.x * 64;
    __shared__ float Ps[16][68];        // [k][t]
    __shared__ float Vs[16][64];        // [k][v]
    int tid = threadIdx.x;
    int tr = tid >> 4, tc = tid & 15;
    float acc[4][4] = {};
    int kmax = t0 + 64;                 // rows t0..t0+63: P zero beyond t
    for (int k0 = 0; k0 < kmax; k0 += 16) {
        {
            int r = tid >> 2, c = (tid & 3) * 4;     // P: 64 rows x 16 k
            float4 pv = *(const float4*)&S[((size_t)bh * TSEQ + t0 + r) * TSEQ + k0 + c];
            Ps[c+0][r] = pv.x; Ps[c+1][r] = pv.y; Ps[c+2][r] = pv.z; Ps[c+3][r] = pv.w;
            int r2 = tid >> 4, c2 = (tid & 15) * 4;  // V: 16 k x 64 cols
            *(float4*)&Vs[r2][c2] =
                *(const float4*)&Vv[((size_t)(b * TSEQ + k0 + r2)) * DMODEL + h * HDIM + c2];
        }
        __syncthreads();
        #pragma unroll
        for (int k = 0; k < 16; k++) {
            float ra[4], rb[4];
            #pragma unroll
            for (int i = 0; i < 4; i++) ra[i] = Ps[k][tr * 4 + i];
            #pragma unroll
            for (int j = 0; j < 4; j++) rb[j] = Vs[k][tc * 4 + j];
            #pragma unroll
            for (int i = 0; i < 4; i++)
                #pragma unroll
                for (int j = 0; j < 4; j++)
                    acc[i][j] += ra[i] * rb[j];
        }
        __syncthreads();
    }
    #pragma unroll
    for (int i = 0; i < 4; i++) {
        size_t ybase = ((size_t)(b * TSEQ + t0 + tr * 4 + i)) * DMODEL + h * HDIM + tc * 4;
        #pragma unroll
        for (int j = 0; j < 4; j++) Y[ybase + j] = acc[i][j];
    }
}

// ---------------- O projection (block-diagonal) + residual into h ----------
__global__ __launch_bounds__(256) void oproj_kernel(const float* __restrict__ Y,
                                                    const float* __restrict__ Wo,
                                                    const float* __restrict__ bo,
                                                    float* __restrict__ H) {
    int h = blockIdx.y;
    int m0 = blockIdx.x * 64;
    __shared__ float Ys[64][68];        // [k][m]
    __shared__ float Ws[64][64];        // [k][n]
    int tid = threadIdx.x;
    #pragma unroll
    for (int i = 0; i < 4; i++) {
        int idx = tid + i * 256;                    // 0..1023
        int r = idx >> 4, c = (idx & 15) * 4;       // 64 x 64
        float4 yv = *(const float4*)&Y[((size_t)(m0 + r)) * DMODEL + h * HDIM + c];
        Ys[c+0][r] = yv.x; Ys[c+1][r] = yv.y; Ys[c+2][r] = yv.z; Ys[c+3][r] = yv.w;
        *(float4*)&Ws[r][c] = *(const float4*)&Wo[((size_t)h * HDIM + r) * HDIM + c];
    }
    __syncthreads();
    int tr = tid >> 4, tc = tid & 15;
    float acc[4][4] = {};
    #pragma unroll
    for (int k = 0; k < 64; k++) {
        float ra[4], rb[4];
        #pragma unroll
        for (int i = 0; i < 4; i++) ra[i] = Ys[k][tr * 4 + i];
        #pragma unroll
        for (int j = 0; j < 4; j++) rb[j] = Ws[k][tc * 4 + j];
        #pragma unroll
        for (int i = 0; i < 4; i++)
            #pragma unroll
            for (int j = 0; j < 4; j++)
                acc[i][j] += ra[i] * rb[j];
    }
    float4 bv = *(const float4*)&bo[h * HDIM + tc * 4];
    #pragma unroll
    for (int i = 0; i < 4; i++) {
        float* hp = &H[((size_t)(m0 + tr * 4 + i)) * DMODEL + h * HDIM + tc * 4];
        float4 r = *(float4*)hp;
        r.x += acc[i][0] + bv.x; r.y += acc[i][1] + bv.y;
        r.z += acc[i][2] + bv.z; r.w += acc[i][3] + bv.w;
        *(float4*)hp = r;
    }
}

// ---------------- driver ----------------------------------------------------
extern "C" void kernel_launch(void* const* d_in, const int* in_sizes, int n_in,
                              void* d_out, int out_size) {
    const int*   x    = (const int*)  d_in[0];
    const float* tok  = (const float*)d_in[1];
    const float* pos  = (const float*)d_in[2];
    const float* Wq   = (const float*)d_in[3];
    const float* bq   = (const float*)d_in[4];
    const float* Wk   = (const float*)d_in[5];
    const float* bk   = (const float*)d_in[6];
    const float* Wv   = (const float*)d_in[7];
    const float* bv   = (const float*)d_in[8];
    const float* Wo   = (const float*)d_in[9];
    const float* bo   = (const float*)d_in[10];
    const float* W1   = (const float*)d_in[11];
    const float* b1   = (const float*)d_in[12];
    const float* W2   = (const float*)d_in[13];
    const float* b2   = (const float*)d_in[14];
    const float* ln1g = (const float*)d_in[15];
    const float* ln1b = (const float*)d_in[16];
    const float* ln2g = (const float*)d_in[17];
    const float* ln2b = (const float*)d_in[18];
    const float* lnfg = (const float*)d_in[19];
    const float* lnfb = (const float*)d_in[20];
    const float* Wout = (const float*)d_in[21];
    const float* bout = (const float*)d_in[22];
    float* out = (float*)d_out;

    float *ph, *pxn, *pq, *pk, *pv, *py, *pff, *ps, *pwq, *pwk, *pwv;
    cudaGetSymbolAddress((void**)&ph,  g_h);
    cudaGetSymbolAddress((void**)&pxn, g_xn);
    cudaGetSymbolAddress((void**)&pq,  g_q);
    cudaGetSymbolAddress((void**)&pk,  g_k);
    cudaGetSymbolAddress((void**)&pv,  g_v);
    cudaGetSymbolAddress((void**)&py,  g_y);
    cudaGetSymbolAddress((void**)&pff, g_ff);
    cudaGetSymbolAddress((void**)&ps,  g_sc);
    cudaGetSymbolAddress((void**)&pwq, g_wq);
    cudaGetSymbolAddress((void**)&pwk, g_wk);
    cudaGetSymbolAddress((void**)&pwv, g_wv);

    repack_kernel<<<4096, 256>>>(Wq, pwq);
    repack_kernel<<<4096, 256>>>(Wk, pwk);
    repack_kernel<<<4096, 256>>>(Wv, pwv);
    embed_kernel<<<NTOK, 256>>>(x, tok, pos, ph);

    for (int layer = 0; layer < NLAYER; layer++) {
        ln_kernel<<<NTOK, 256>>>(ph, ln1g, ln1b, pxn);

        dim3 gqkv(DMODEL / 128, NTOK / 128);
        sgemm_kernel<0><<<gqkv, 256>>>(pxn, pwq, bq, pq, NTOK, DMODEL, DMODEL);
        sgemm_kernel<0><<<gqkv, 256>>>(pxn, pwk, bk, pk, NTOK, DMODEL, DMODEL);
        sgemm_kernel<0><<<gqkv, 256>>>(pxn, pwv, bv, pv, NTOK, DMODEL, DMODEL);

        scores_kernel<<<dim3(TSEQ / 32, TSEQ / 32, BATCH * NHEAD), 256>>>(pq, pk, ps);
        softmax_kernel<<<BATCH * NHEAD * TSEQ, 256>>>(ps);
        av_kernel<<<dim3(TSEQ / 64, BATCH * NHEAD), 256>>>(ps, pv, py);
        oproj_kernel<<<dim3(NTOK / 64, NHEAD), 256>>>(py, Wo, bo, ph);

        ln_kernel<<<NTOK, 256>>>(ph, ln2g, ln2b, pxn);
        sgemm_kernel<1><<<dim3(FFDIM / 128, NTOK / 128), 256>>>(pxn, W1, b1, pff,
                                                               NTOK, FFDIM, DMODEL);
        sgemm_kernel<2><<<dim3(DMODEL / 128, NTOK / 128), 256>>>(pff, W2, b2, ph,
                                                                NTOK, DMODEL, FFDIM);
    }

    ln_kernel<<<NTOK, 256>>>(ph, lnfg, lnfb, pxn);
    sgemm_kernel<0><<<dim3(VOCAB / 128, NTOK / 128), 256>>>(pxn, Wout, bout, out,
                                                            NTOK, VOCAB, DMODEL);
}

// round 3
// speedup vs baseline: 3.7943x; 3.7943x over previous
#include <cuda_runtime.h>
#include <cuda_fp16.h>
#include <math.h>
#include <float.h>
#include <stdint.h>

// Problem constants
#define BATCH   4
#define TSEQ    1024
#define DMODEL  1024
#define NHEAD   16
#define HDIM    64
#define NLAYER  4
#define VOCAB   32000
#define NTOK    (BATCH*TSEQ)        // 4096 rows
#define FFDIM   (4*DMODEL)          // 4096

// ---------------- scratch (device globals; no allocation allowed) ----------
__device__ float  g_h   [(size_t)NTOK*DMODEL];
__device__ __half g_xn16[(size_t)NTOK*DMODEL];
__device__ float  g_q   [(size_t)NTOK*DMODEL];
__device__ float  g_k   [(size_t)NTOK*DMODEL];
__device__ float  g_v   [(size_t)NTOK*DMODEL];
__device__ float  g_y   [(size_t)NTOK*DMODEL];
__device__ __half g_ff16[(size_t)NTOK*FFDIM];
__device__ float  g_sc  [(size_t)BATCH*NHEAD*TSEQ*TSEQ];
__device__ __half g_wqkv[(size_t)3*DMODEL*DMODEL];   // [3072, 1024] K-major
__device__ float  g_bqkv[3*DMODEL];
__device__ __half g_w1t [(size_t)FFDIM*DMODEL];      // [4096, 1024]
__device__ __half g_w2t [(size_t)DMODEL*FFDIM];      // [1024, 4096]
__device__ __half g_woT [(size_t)VOCAB*DMODEL];      // [32000, 1024]

// ======================= PTX helpers ========================================
__device__ __forceinline__ uint32_t smem_u32(const void* p) {
    uint32_t a;
    asm("{ .reg .u64 t; cvta.to.shared.u64 t, %1; cvt.u32.u64 %0, t; }"
        : "=r"(a) : "l"(p));
    return a;
}
__device__ __forceinline__ void cpa16(uint32_t dst, const void* src) {
    asm volatile("cp.async.cg.shared.global [%0], [%1], 16;" :: "r"(dst), "l"(src));
}
#define CP_COMMIT() asm volatile("cp.async.commit_group;" ::: "memory")
#define CP_WAIT(n)  asm volatile("cp.async.wait_group %0;" :: "n"(n) : "memory")

__device__ __forceinline__ void ldsm4(uint32_t* r, uint32_t a) {
    asm volatile("ldmatrix.sync.aligned.m8n8.x4.shared.b16 {%0,%1,%2,%3}, [%4];"
        : "=r"(r[0]), "=r"(r[1]), "=r"(r[2]), "=r"(r[3]) : "r"(a));
}
__device__ __forceinline__ void ldsm2(uint32_t* r, uint32_t a) {
    asm volatile("ldmatrix.sync.aligned.m8n8.x2.shared.b16 {%0,%1}, [%2];"
        : "=r"(r[0]), "=r"(r[1]) : "r"(a));
}
__device__ __forceinline__ void mma16816(float* c, const uint32_t* a, const uint32_t* b) {
    asm volatile("mma.sync.aligned.m16n8k16.row.col.f32.f16.f16.f32 "
        "{%0,%1,%2,%3}, {%4,%5,%6,%7}, {%8,%9}, {%0,%1,%2,%3};"
        : "+f"(c[0]), "+f"(c[1]), "+f"(c[2]), "+f"(c[3])
        : "r"(a[0]), "r"(a[1]), "r"(a[2]), "r"(a[3]), "r"(b[0]), "r"(b[1]));
}

// ======================= HMMA GEMM ==========================================
// C[M,N] = A[M,K](fp16 row-major) @ B[N,K](fp16 K-major)^T + bias
// Block tile 128x128x32, 256 threads (8 warps, 2x4), warp tile 64x32.
// MODE 0: fp32 out   MODE 1: relu -> fp16 out (Ch)
// MODE 2: fp32 += (residual into Cq)
// MODE 3: QKV split: N-chunks of 1024 -> Cq / Ck / Cv
#define BM 128
#define BN 128
#define BK 32
#define ASTR 80   // bytes per 32-half row (64B data + 16B pad): conflict-free ldmatrix

template<int MODE>
__global__ __launch_bounds__(256)
void tgemm(const __half* __restrict__ A, const __half* __restrict__ B,
           const float* __restrict__ bias,
           float* Cq, float* Ck, float* Cv, __half* Ch,
           int N, int K) {
    __shared__ __align__(16) char sA[2][BM * ASTR];
    __shared__ __align__(16) char sB[2][BN * ASTR];
    const int tid = threadIdx.x;
    const int w = tid >> 5, lane = tid & 31;
    const int wm = w & 1, wn = w >> 1;         // warp tile: rows wm*64, cols wn*32
    const int bm = blockIdx.x * BM, bn = blockIdx.y * BN;

    const __half* Ab = A + (size_t)bm * K;
    const __half* Bb = B + (size_t)bn * K;
    const int row_l = tid >> 2, ch_l = tid & 3;       // loader mapping (2 iters)

    auto load_stage = [&](int s, int buf) {
        const __half* As = Ab + s * BK;
        const __half* Bs = Bb + s * BK;
        #pragma unroll
        for (int i = 0; i < 2; i++) {
            int r = row_l + i * 64;
            cpa16(smem_u32(&sA[buf][r * ASTR + ch_l * 16]), As + (size_t)r * K + ch_l * 8);
            cpa16(smem_u32(&sB[buf][r * ASTR + ch_l * 16]), Bs + (size_t)r * K + ch_l * 8);
        }
    };

    float acc[4][4][4] = {};
    const int S = K / BK;

    load_stage(0, 0); CP_COMMIT();
    load_stage(1, 1); CP_COMMIT();

    for (int s = 0; s < S; s++) {
        if (s < S - 1) { CP_WAIT(1); } else { CP_WAIT(0); }
        __syncthreads();
        const int buf = s & 1;
        uint32_t ab = smem_u32(&sA[buf][0]);
        uint32_t bb = smem_u32(&sB[buf][0]);
        #pragma unroll
        for (int ks = 0; ks < 2; ks++) {
            uint32_t af[4][4], bf[4][2];
            #pragma unroll
            for (int mi = 0; mi < 4; mi++) {
                int r = wm * 64 + mi * 16 + (lane & 15);
                ldsm4(af[mi], ab + r * ASTR + ks * 32 + ((lane >> 4) << 4));
            }
            #pragma unroll
            for (int nj = 0; nj < 4; nj++) {
                int r = wn * 32 + nj * 8 + (lane & 7);
                ldsm2(bf[nj], bb + r * ASTR + ks * 32 + (((lane >> 3) & 1) << 4));
            }
            #pragma unroll
            for (int mi = 0; mi < 4; mi++)
                #pragma unroll
                for (int nj = 0; nj < 4; nj++)
                    mma16816(acc[mi][nj], af[mi], bf[nj]);
        }
        __syncthreads();
        if (s + 2 < S) { load_stage(s + 2, buf); CP_COMMIT(); }
    }

    // epilogue: C fragment: (row = lane/4 [+8], col = 2*(lane%4)+{0,1})
    const int l4 = lane >> 2, l2 = (lane & 3) * 2;
    #pragma unroll
    for (int mi = 0; mi < 4; mi++) {
        int m0 = bm + wm * 64 + mi * 16 + l4;
        #pragma unroll
        for (int nj = 0; nj < 4; nj++) {
            int ng = bn + wn * 32 + nj * 8 + l2;      // global col
            float b0 = bias[ng], b1 = bias[ng + 1];
            float v00 = acc[mi][nj][0] + b0, v01 = acc[mi][nj][1] + b1;
            float v10 = acc[mi][nj][2] + b0, v11 = acc[mi][nj][3] + b1;
            if (MODE == 3) {
                int which = bn >> 10;
                float* dst = (which == 0) ? Cq : (which == 1) ? Ck : Cv;
                int nc = ng & 1023;
                *(float2*)(dst + (size_t)m0 * DMODEL + nc)       = make_float2(v00, v01);
                *(float2*)(dst + (size_t)(m0 + 8) * DMODEL + nc) = make_float2(v10, v11);
            } else if (MODE == 1) {
                *(__half2*)(Ch + (size_t)m0 * N + ng) =
                    __floats2half2_rn(fmaxf(v00, 0.f), fmaxf(v01, 0.f));
                *(__half2*)(Ch + (size_t)(m0 + 8) * N + ng) =
                    __floats2half2_rn(fmaxf(v10, 0.f), fmaxf(v11, 0.f));
            } else {
                float* p0 = Cq + (size_t)m0 * N + ng;
                float* p1 = Cq + (size_t)(m0 + 8) * N + ng;
                if (MODE == 2) {
                    float2 o0 = *(float2*)p0, o1 = *(float2*)p1;
                    v00 += o0.x; v01 += o0.y; v10 += o1.x; v11 += o1.y;
                }
                *(float2*)p0 = make_float2(v00, v01);
                *(float2*)p1 = make_float2(v10, v11);
            }
        }
    }
}

// ======================= misc kernels ======================================
template<bool DOMAX>
__device__ __forceinline__ float block_reduce(float x) {
    #pragma unroll
    for (int o = 16; o; o >>= 1) {
        float t = __shfl_xor_sync(0xFFFFFFFFu, x, o);
        x = DOMAX ? fmaxf(x, t) : x + t;
    }
    __shared__ float sh[8];
    int w = threadIdx.x >> 5;
    __syncthreads();
    if ((threadIdx.x & 31) == 0) sh[w] = x;
    __syncthreads();
    float r = sh[0];
    #pragma unroll
    for (int i = 1; i < 8; i++) r = DOMAX ? fmaxf(r, sh[i]) : r + sh[i];
    return r;
}

__global__ __launch_bounds__(256) void embed_kernel(const int* __restrict__ x,
                                                    const float* __restrict__ tok,
                                                    const float* __restrict__ pos,
                                                    float* __restrict__ H) {
    int row = blockIdx.x;
    int tid = row % TSEQ;
    size_t tb = (size_t)x[row] * DMODEL, pb = (size_t)tid * DMODEL;
    size_t hb = (size_t)row * DMODEL;
    #pragma unroll
    for (int i = 0; i < 4; i++) {
        int c = threadIdx.x + i * 256;
        H[hb + c] = tok[tb + c] + pos[pb + c];
    }
}

// layernorm: fp32 in -> fp16 out
__global__ __launch_bounds__(256) void ln_kernel(const float* __restrict__ X,
                                                 const float* __restrict__ g,
                                                 const float* __restrict__ b,
                                                 __half* __restrict__ O) {
    size_t base = (size_t)blockIdx.x * DMODEL;
    float v[4], s = 0.f, sq = 0.f;
    #pragma unroll
    for (int i = 0; i < 4; i++) {
        v[i] = X[base + threadIdx.x + i * 256];
        s += v[i]; sq += v[i] * v[i];
    }
    s  = block_reduce<false>(s);
    sq = block_reduce<false>(sq);
    float mu = s * (1.f / DMODEL);
    float rstd = rsqrtf(sq * (1.f / DMODEL) - mu * mu + 1e-5f);
    #pragma unroll
    for (int i = 0; i < 4; i++) {
        int c = threadIdx.x + i * 256;
        O[base + c] = __float2half((v[i] - mu) * rstd * g[c] + b[c]);
    }
}

// scores: 64x64 tiles, causal-skipped
__global__ __launch_bounds__(256) void scores_kernel(const float* __restrict__ Q,
                                                     const float* __restrict__ Kv,
                                                     float* __restrict__ S) {
    int t0 = blockIdx.y * 64, s0 = blockIdx.x * 64;
    if (s0 > t0 + 63) return;
    int bh = blockIdx.z, b = bh >> 4, h = bh & 15;
    __shared__ float Qs[64][68];
    __shared__ float Ks[64][68];
    int tid = threadIdx.x;
    #pragma unroll
    for (int i = 0; i < 4; i++) {
        int idx = tid + i * 256;
        int r = idx >> 4, c = (idx & 15) * 4;
        float4 qv = *(const float4*)&Q[((size_t)(b*TSEQ + t0 + r))*DMODEL + h*HDIM + c];
        Qs[c+0][r] = qv.x; Qs[c+1][r] = qv.y; Qs[c+2][r] = qv.z; Qs[c+3][r] = qv.w;
        float4 kv = *(const float4*)&Kv[((size_t)(b*TSEQ + s0 + r))*DMODEL + h*HDIM + c];
        Ks[c+0][r] = kv.x; Ks[c+1][r] = kv.y; Ks[c+2][r] = kv.z; Ks[c+3][r] = kv.w;
    }
    __syncthreads();
    int tr = tid >> 4, tc = tid & 15;
    float acc[4][4] = {};
    #pragma unroll
    for (int k = 0; k < 64; k++) {
        float ra[4], rb[4];
        #pragma unroll
        for (int i = 0; i < 4; i++) ra[i] = Qs[k][tr * 4 + i];
        #pragma unroll
        for (int j = 0; j < 4; j++) rb[j] = Ks[k][tc * 4 + j];
        #pragma unroll
        for (int i = 0; i < 4; i++)
            #pragma unroll
            for (int j = 0; j < 4; j++)
                acc[i][j] += ra[i] * rb[j];
    }
    const float scale = 0.125f;
    #pragma unroll
    for (int i = 0; i < 4; i++) {
        size_t rb0 = ((size_t)bh * TSEQ + t0 + tr*4 + i) * TSEQ + s0 + tc*4;
        float4 o = make_float4(acc[i][0]*scale, acc[i][1]*scale,
                               acc[i][2]*scale, acc[i][3]*scale);
        *(float4*)&S[rb0] = o;
    }
}

__global__ __launch_bounds__(256) void softmax_kernel(float* __restrict__ S) {
    int row = blockIdx.x;
    int t = row & (TSEQ - 1);
    float* sr = S + (size_t)row * TSEQ;
    float v[4], mx = -FLT_MAX;
    #pragma unroll
    for (int i = 0; i < 4; i++) {
        int s = threadIdx.x + i * 256;
        float val = sr[s];
        if (s > t || val == 0.0f) val = -FLT_MAX;
        v[i] = val; mx = fmaxf(mx, val);
    }
    float M = block_reduce<true>(mx);
    float sum = 0.f;
    #pragma unroll
    for (int i = 0; i < 4; i++) {
        float e = (v[i] == -FLT_MAX) ? 0.f : expf(v[i] - M);
        v[i] = e; sum += e;
    }
    sum = block_reduce<false>(sum);
    float inv = 1.f / sum;
    #pragma unroll
    for (int i = 0; i < 4; i++)
        sr[threadIdx.x + i * 256] = v[i] * inv;
}

__global__ __launch_bounds__(256) void av_kernel(const float* __restrict__ S,
                                                 const float* __restrict__ Vv,
                                                 float* __restrict__ Y) {
    int bh = blockIdx.y, b = bh >> 4, h = bh & 15;
    int t0 = blockIdx.x * 64;
    __shared__ float Ps[16][68];
    __shared__ float Vs[16][64];
    int tid = threadIdx.x;
    int tr = tid >> 4, tc = tid & 15;
    float acc[4][4] = {};
    int kmax = t0 + 64;
    for (int k0 = 0; k0 < kmax; k0 += 16) {
        {
            int r = tid >> 2, c = (tid & 3) * 4;
            float4 pv = *(const float4*)&S[((size_t)bh*TSEQ + t0 + r)*TSEQ + k0 + c];
            Ps[c+0][r] = pv.x; Ps[c+1][r] = pv.y; Ps[c+2][r] = pv.z; Ps[c+3][r] = pv.w;
            int r2 = tid >> 4, c2 = (tid & 15) * 4;
            *(float4*)&Vs[r2][c2] =
                *(const float4*)&Vv[((size_t)(b*TSEQ + k0 + r2))*DMODEL + h*HDIM + c2];
        }
        __syncthreads();
        #pragma unroll
        for (int k = 0; k < 16; k++) {
            float ra[4], rb[4];
            #pragma unroll
            for (int i = 0; i < 4; i++) ra[i] = Ps[k][tr * 4 + i];
            #pragma unroll
            for (int j = 0; j < 4; j++) rb[j] = Vs[k][tc * 4 + j];
            #pragma unroll
            for (int i = 0; i < 4; i++)
                #pragma unroll
                for (int j = 0; j < 4; j++)
                    acc[i][j] += ra[i] * rb[j];
        }
        __syncthreads();
    }
    #pragma unroll
    for (int i = 0; i < 4; i++) {
        size_t yb = ((size_t)(b*TSEQ + t0 + tr*4 + i))*DMODEL + h*HDIM + tc*4;
        #pragma unroll
        for (int j = 0; j < 4; j++) Y[yb + j] = acc[i][j];
    }
}

__global__ __launch_bounds__(256) void oproj_kernel(const float* __restrict__ Y,
                                                    const float* __restrict__ Wo,
                                                    const float* __restrict__ bo,
                                                    float* __restrict__ H) {
    int h = blockIdx.y;
    int m0 = blockIdx.x * 64;
    __shared__ float Ys[64][68];
    __shared__ float Ws[64][64];
    int tid = threadIdx.x;
    #pragma unroll
    for (int i = 0; i < 4; i++) {
        int idx = tid + i * 256;
        int r = idx >> 4, c = (idx & 15) * 4;
        float4 yv = *(const float4*)&Y[((size_t)(m0 + r))*DMODEL + h*HDIM + c];
        Ys[c+0][r] = yv.x; Ys[c+1][r] = yv.y; Ys[c+2][r] = yv.z; Ys[c+3][r] = yv.w;
        *(float4*)&Ws[r][c] = *(const float4*)&Wo[((size_t)h*HDIM + r)*HDIM + c];
    }
    __syncthreads();
    int tr = tid >> 4, tc = tid & 15;
    float acc[4][4] = {};
    #pragma unroll
    for (int k = 0; k < 64; k++) {
        float ra[4], rb[4];
        #pragma unroll
        for (int i = 0; i < 4; i++) ra[i] = Ys[k][tr * 4 + i];
        #pragma unroll
        for (int j = 0; j < 4; j++) rb[j] = Ws[k][tc * 4 + j];
        #pragma unroll
        for (int i = 0; i < 4; i++)
            #pragma unroll
            for (int j = 0; j < 4; j++)
                acc[i][j] += ra[i] * rb[j];
    }
    float4 bv = *(const float4*)&bo[h * HDIM + tc * 4];
    #pragma unroll
    for (int i = 0; i < 4; i++) {
        float* hp = &H[((size_t)(m0 + tr*4 + i))*DMODEL + h*HDIM + tc*4];
        float4 r = *(float4*)hp;
        r.x += acc[i][0] + bv.x; r.y += acc[i][1] + bv.y;
        r.z += acc[i][2] + bv.z; r.w += acc[i][3] + bv.w;
        *(float4*)hp = r;
    }
}

// transpose fp32 [R,C] -> fp16 [C,R]
__global__ void transpose16(const float* __restrict__ S, __half* __restrict__ D,
                            int R, int C) {
    __shared__ float t[32][33];
    int c0 = blockIdx.x * 32, r0 = blockIdx.y * 32;
    #pragma unroll
    for (int i = 0; i < 4; i++)
        t[threadIdx.y + i*8][threadIdx.x] =
            S[(size_t)(r0 + threadIdx.y + i*8) * C + c0 + threadIdx.x];
    __syncthreads();
    #pragma unroll
    for (int i = 0; i < 4; i++)
        D[(size_t)(c0 + threadIdx.y + i*8) * R + r0 + threadIdx.x] =
            __float2half(t[threadIdx.x][threadIdx.y + i*8]);
}

// Wq/Wk/Wv [H, D, 64] -> dst [H*64, D] fp16 (per-head transpose)
__global__ void repack_headT(const float* __restrict__ W, __half* __restrict__ D) {
    __shared__ float t[32][33];
    int h = blockIdx.z;
    int k0 = blockIdx.x * 32, d0 = blockIdx.y * 32;
    #pragma unroll
    for (int i = 0; i < 4; i++)
        t[threadIdx.y + i*8][threadIdx.x] =
            W[((size_t)(h*DMODEL + d0 + threadIdx.y + i*8)) * HDIM + k0 + threadIdx.x];
    __syncthreads();
    #pragma unroll
    for (int i = 0; i < 4; i++)
        D[((size_t)(h*HDIM + k0 + threadIdx.y + i*8)) * DMODEL + d0 + threadIdx.x] =
            __float2half(t[threadIdx.x][threadIdx.y + i*8]);
}

__global__ void catbias(const float* a, const float* b, const float* c, float* o) {
    int i = blockIdx.x * 256 + threadIdx.x;
    o[i] = (i < 1024) ? a[i] : (i < 2048) ? b[i - 1024] : c[i - 2048];
}

// ---------------- driver ----------------------------------------------------
extern "C" void kernel_launch(void* const* d_in, const int* in_sizes, int n_in,
                              void* d_out, int out_size) {
    const int*   x    = (const int*)  d_in[0];
    const float* tok  = (const float*)d_in[1];
    const float* pos  = (const float*)d_in[2];
    const float* Wq   = (const float*)d_in[3];
    const float* bq   = (const float*)d_in[4];
    const float* Wk   = (const float*)d_in[5];
    const float* bk   = (const float*)d_in[6];
    const float* Wv   = (const float*)d_in[7];
    const float* bv   = (const float*)d_in[8];
    const float* Wo   = (const float*)d_in[9];
    const float* bo   = (const float*)d_in[10];
    const float* W1   = (const float*)d_in[11];
    const float* b1   = (const float*)d_in[12];
    const float* W2   = (const float*)d_in[13];
    const float* b2   = (const float*)d_in[14];
    const float* ln1g = (const float*)d_in[15];
    const float* ln1b = (const float*)d_in[16];
    const float* ln2g = (const float*)d_in[17];
    const float* ln2b = (const float*)d_in[18];
    const float* lnfg = (const float*)d_in[19];
    const float* lnfb = (const float*)d_in[20];
    const float* Wout = (const float*)d_in[21];
    const float* bout = (const float*)d_in[22];
    float* out = (float*)d_out;

    float *ph, *pq, *pk, *pv, *py, *ps, *pbqkv;
    __half *pxn, *pff, *pwqkv, *pw1t, *pw2t, *pwoT;
    cudaGetSymbolAddress((void**)&ph,    g_h);
    cudaGetSymbolAddress((void**)&pxn,   g_xn16);
    cudaGetSymbolAddress((void**)&pq,    g_q);
    cudaGetSymbolAddress((void**)&pk,    g_k);
    cudaGetSymbolAddress((void**)&pv,    g_v);
    cudaGetSymbolAddress((void**)&py,    g_y);
    cudaGetSymbolAddress((void**)&pff,   g_ff16);
    cudaGetSymbolAddress((void**)&ps,    g_sc);
    cudaGetSymbolAddress((void**)&pwqkv, g_wqkv);
    cudaGetSymbolAddress((void**)&pbqkv, g_bqkv);
    cudaGetSymbolAddress((void**)&pw1t,  g_w1t);
    cudaGetSymbolAddress((void**)&pw2t,  g_w2t);
    cudaGetSymbolAddress((void**)&pwoT,  g_woT);

    dim3 tb(32, 8);
    repack_headT<<<dim3(2, 32, 16), tb>>>(Wq, pwqkv);
    repack_headT<<<dim3(2, 32, 16), tb>>>(Wk, pwqkv + (size_t)DMODEL*DMODEL);
    repack_headT<<<dim3(2, 32, 16), tb>>>(Wv, pwqkv + (size_t)2*DMODEL*DMODEL);
    catbias<<<12, 256>>>(bq, bk, bv, pbqkv);
    transpose16<<<dim3(FFDIM/32, DMODEL/32), tb>>>(W1, pw1t, DMODEL, FFDIM);
    transpose16<<<dim3(DMODEL/32, FFDIM/32), tb>>>(W2, pw2t, FFDIM, DMODEL);
    transpose16<<<dim3(VOCAB/32, DMODEL/32), tb>>>(Wout, pwoT, DMODEL, VOCAB);

    embed_kernel<<<NTOK, 256>>>(x, tok, pos, ph);

    for (int layer = 0; layer < NLAYER; layer++) {
        ln_kernel<<<NTOK, 256>>>(ph, ln1g, ln1b, pxn);
        tgemm<3><<<dim3(NTOK/BM, 3*DMODEL/BN), 256>>>(
            pxn, pwqkv, pbqkv, pq, pk, pv, nullptr, 3*DMODEL, DMODEL);

        scores_kernel<<<dim3(TSEQ/64, TSEQ/64, BATCH*NHEAD), 256>>>(pq, pk, ps);
        softmax_kernel<<<BATCH*NHEAD*TSEQ, 256>>>(ps);
        av_kernel<<<dim3(TSEQ/64, BATCH*NHEAD), 256>>>(ps, pv, py);
        oproj_kernel<<<dim3(NTOK/64, NHEAD), 256>>>(py, Wo, bo, ph);

        ln_kernel<<<NTOK, 256>>>(ph, ln2g, ln2b, pxn);
        tgemm<1><<<dim3(NTOK/BM, FFDIM/BN), 256>>>(
            pxn, pw1t, b1, nullptr, nullptr, nullptr, pff, FFDIM, DMODEL);
        tgemm<2><<<dim3(NTOK/BM, DMODEL/BN), 256>>>(
            pff, pw2t, b2, ph, nullptr, nullptr, nullptr, DMODEL, FFDIM);
    }

    ln_kernel<<<NTOK, 256>>>(ph, lnfg, lnfb, pxn);
    tgemm<0><<<dim3(NTOK/BM, VOCAB/BN), 256>>>(
        pxn, pwoT, bout, out, nullptr, nullptr, nullptr, VOCAB, DMODEL);
}

// round 6
// speedup vs baseline: 5.6541x; 1.4902x over previous
#include <cuda_runtime.h>
#include <cuda_fp16.h>
#include <math.h>
#include <float.h>
#include <stdint.h>

// Problem constants
#define BATCH   4
#define TSEQ    1024
#define DMODEL  1024
#define NHEAD   16
#define HDIM    64
#define NLAYER  4
#define VOCAB   32000
#define NTOK    (BATCH*TSEQ)        // 4096 rows
#define FFDIM   (4*DMODEL)          // 4096

// ---------------- scratch (device globals; no allocation allowed) ----------
__device__ float  g_h   [(size_t)NTOK*DMODEL];
__device__ __half g_xn16[(size_t)NTOK*DMODEL];
__device__ __half g_q16 [(size_t)NTOK*DMODEL];
__device__ __half g_k16 [(size_t)NTOK*DMODEL];
__device__ __half g_v16 [(size_t)NTOK*DMODEL];
__device__ float  g_y   [(size_t)NTOK*DMODEL];
__device__ __half g_ff16[(size_t)NTOK*FFDIM];
__device__ __half g_wqkv[(size_t)3*DMODEL*DMODEL];   // [3072, 1024] K-major
__device__ float  g_bqkv[3*DMODEL];
__device__ __half g_w1t [(size_t)FFDIM*DMODEL];      // [4096, 1024]
__device__ __half g_w2t [(size_t)DMODEL*FFDIM];      // [1024, 4096]
__device__ __half g_woT [(size_t)VOCAB*DMODEL];      // [32000, 1024]

// ======================= PTX helpers ========================================
__device__ __forceinline__ uint32_t smem_u32(const void* p) {
    uint32_t a;
    asm("{ .reg .u64 t; cvta.to.shared.u64 t, %1; cvt.u32.u64 %0, t; }"
        : "=r"(a) : "l"(p));
    return a;
}
__device__ __forceinline__ uint32_t h2u(__half2 h) {
    union { __half2 h; uint32_t u; } cvt;
    cvt.h = h;
    return cvt.u;
}
__device__ __forceinline__ void cpa16(uint32_t dst, const void* src) {
    asm volatile("cp.async.cg.shared.global [%0], [%1], 16;" :: "r"(dst), "l"(src));
}
#define CP_COMMIT() asm volatile("cp.async.commit_group;" ::: "memory")
#define CP_WAIT(n)  asm volatile("cp.async.wait_group %0;" :: "n"(n) : "memory")

__device__ __forceinline__ void ldsm4(uint32_t* r, uint32_t a) {
    asm volatile("ldmatrix.sync.aligned.m8n8.x4.shared.b16 {%0,%1,%2,%3}, [%4];"
        : "=r"(r[0]), "=r"(r[1]), "=r"(r[2]), "=r"(r[3]) : "r"(a));
}
__device__ __forceinline__ void ldsm2(uint32_t* r, uint32_t a) {
    asm volatile("ldmatrix.sync.aligned.m8n8.x2.shared.b16 {%0,%1}, [%2];"
        : "=r"(r[0]), "=r"(r[1]) : "r"(a));
}
__device__ __forceinline__ void ldsm2t(uint32_t* r, uint32_t a) {
    asm volatile("ldmatrix.sync.aligned.m8n8.x2.trans.shared.b16 {%0,%1}, [%2];"
        : "=r"(r[0]), "=r"(r[1]) : "r"(a));
}
__device__ __forceinline__ void mma16816(float* c, const uint32_t* a, const uint32_t* b) {
    asm volatile("mma.sync.aligned.m16n8k16.row.col.f32.f16.f16.f32 "
        "{%0,%1,%2,%3}, {%4,%5,%6,%7}, {%8,%9}, {%0,%1,%2,%3};"
        : "+f"(c[0]), "+f"(c[1]), "+f"(c[2]), "+f"(c[3])
        : "r"(a[0]), "r"(a[1]), "r"(a[2]), "r"(a[3]), "r"(b[0]), "r"(b[1]));
}

// ======================= HMMA GEMM ==========================================
// C[M,N] = A[M,K](fp16 row-major) @ B[N,K](fp16 K-major)^T + bias
// MODE 0: fp32 out (Cf)   MODE 1: relu -> fp16 (Ch)
// MODE 2: fp32 += (residual into Cf)
// MODE 3: QKV split -> fp16 Ch/Chk/Chv (N-chunks of 1024)
#define BM 128
#define BN 128
#define BK 32
#define ASTR 80   // bytes per 32-half row (64B data + 16B pad)

template<int MODE>
__global__ __launch_bounds__(256)
void tgemm(const __half* __restrict__ A, const __half* __restrict__ B,
           const float* __restrict__ bias,
           float* Cf, __half* Ch, __half* Chk, __half* Chv,
           int N, int K) {
    __shared__ __align__(16) char sA[2][BM * ASTR];
    __shared__ __align__(16) char sB[2][BN * ASTR];
    const int tid = threadIdx.x;
    const int w = tid >> 5, lane = tid & 31;
    const int wm = w & 1, wn = w >> 1;
    const int bm = blockIdx.x * BM, bn = blockIdx.y * BN;

    const __half* Ab = A + (size_t)bm * K;
    const __half* Bb = B + (size_t)bn * K;
    const int row_l = tid >> 2, ch_l = tid & 3;

    auto load_stage = [&](int s, int buf) {
        const __half* As = Ab + s * BK;
        const __half* Bs = Bb + s * BK;
        #pragma unroll
        for (int i = 0; i < 2; i++) {
            int r = row_l + i * 64;
            cpa16(smem_u32(&sA[buf][r * ASTR + ch_l * 16]), As + (size_t)r * K + ch_l * 8);
            cpa16(smem_u32(&sB[buf][r * ASTR + ch_l * 16]), Bs + (size_t)r * K + ch_l * 8);
        }
    };

    float acc[4][4][4] = {};
    const int S = K / BK;

    load_stage(0, 0); CP_COMMIT();
    load_stage(1, 1); CP_COMMIT();

    for (int s = 0; s < S; s++) {
        if (s < S - 1) { CP_WAIT(1); } else { CP_WAIT(0); }
        __syncthreads();
        const int buf = s & 1;
        uint32_t ab = smem_u32(&sA[buf][0]);
        uint32_t bb = smem_u32(&sB[buf][0]);
        #pragma unroll
        for (int ks = 0; ks < 2; ks++) {
            uint32_t af[4][4], bf[4][2];
            #pragma unroll
            for (int mi = 0; mi < 4; mi++) {
                int r = wm * 64 + mi * 16 + (lane & 15);
                ldsm4(af[mi], ab + r * ASTR + ks * 32 + ((lane >> 4) << 4));
            }
            #pragma unroll
            for (int nj = 0; nj < 4; nj++) {
                int r = wn * 32 + nj * 8 + (lane & 7);
                ldsm2(bf[nj], bb + r * ASTR + ks * 32 + (((lane >> 3) & 1) << 4));
            }
            #pragma unroll
            for (int mi = 0; mi < 4; mi++)
                #pragma unroll
                for (int nj = 0; nj < 4; nj++)
                    mma16816(acc[mi][nj], af[mi], bf[nj]);
        }
        __syncthreads();
        if (s + 2 < S) { load_stage(s + 2, buf); CP_COMMIT(); }
    }

    const int l4 = lane >> 2, l2 = (lane & 3) * 2;
    #pragma unroll
    for (int mi = 0; mi < 4; mi++) {
        int m0 = bm + wm * 64 + mi * 16 + l4;
        #pragma unroll
        for (int nj = 0; nj < 4; nj++) {
            int ng = bn + wn * 32 + nj * 8 + l2;
            float b0 = bias[ng], b1 = bias[ng + 1];
            float v00 = acc[mi][nj][0] + b0, v01 = acc[mi][nj][1] + b1;
            float v10 = acc[mi][nj][2] + b0, v11 = acc[mi][nj][3] + b1;
            if (MODE == 3) {
                int which = bn >> 10;
                __half* dst = (which == 0) ? Ch : (which == 1) ? Chk : Chv;
                int nc = ng & 1023;
                *(__half2*)(dst + (size_t)m0 * DMODEL + nc)       = __floats2half2_rn(v00, v01);
                *(__half2*)(dst + (size_t)(m0 + 8) * DMODEL + nc) = __floats2half2_rn(v10, v11);
            } else if (MODE == 1) {
                *(__half2*)(Ch + (size_t)m0 * N + ng) =
                    __floats2half2_rn(fmaxf(v00, 0.f), fmaxf(v01, 0.f));
                *(__half2*)(Ch + (size_t)(m0 + 8) * N + ng) =
                    __floats2half2_rn(fmaxf(v10, 0.f), fmaxf(v11, 0.f));
            } else {
                float* p0 = Cf + (size_t)m0 * N + ng;
                float* p1 = Cf + (size_t)(m0 + 8) * N + ng;
                if (MODE == 2) {
                    float2 o0 = *(float2*)p0, o1 = *(float2*)p1;
                    v00 += o0.x; v01 += o0.y; v10 += o1.x; v11 += o1.y;
                }
                *(float2*)p0 = make_float2(v00, v01);
                *(float2*)p1 = make_float2(v10, v11);
            }
        }
    }
}

// ======================= fused flash attention =============================
// One block per (t-block of 64 rows, b*h). 128 threads = 4 warps; warp w owns
// rows w*16..w*16+15. Loops over s-blocks of 64 (causal). Exact source-quirk
// mask: scale, then (s>t || val==0) -> -inf. Online softmax in fp32.
#define FSTR 144   // 64 halves (128B) + 16B pad per row

__global__ __launch_bounds__(128)
void fattn_kernel(const __half* __restrict__ Q, const __half* __restrict__ K,
                  const __half* __restrict__ V, float* __restrict__ Y) {
    __shared__ __align__(16) char sQ[64 * FSTR];
    __shared__ __align__(16) char sK[64 * FSTR];
    __shared__ __align__(16) char sV[64 * FSTR];
    const int t0 = blockIdx.x * 64;
    const int bh = blockIdx.y, b = bh >> 4, h = bh & 15;
    const int tid = threadIdx.x, w = tid >> 5, lane = tid & 31;
    const int l4 = lane >> 2, l2 = (lane & 3) * 2;
    const size_t base = (size_t)b * TSEQ * DMODEL + h * HDIM;

    // load Q tile (64 x 64 halfs)
    #pragma unroll
    for (int i = 0; i < 4; i++) {
        int idx = tid + i * 128;
        int r = idx >> 3, cseg = idx & 7;
        *(uint4*)(sQ + r * FSTR + cseg * 16) =
            *(const uint4*)(Q + base + (size_t)(t0 + r) * DMODEL + cseg * 8);
    }

    uint32_t sqb = smem_u32(sQ), skb = smem_u32(sK), svb = smem_u32(sV);
    uint32_t qf[4][4];
    float m_run[2] = {-FLT_MAX, -FLT_MAX};
    float l_run[2] = {0.f, 0.f};
    float o[8][4] = {};
    const int tg0 = t0 + w * 16 + l4;      // global rows this thread owns
    const int tg1 = tg0 + 8;

    for (int s0 = 0; s0 <= t0; s0 += 64) {
        __syncthreads();   // smem reuse guard (also covers sQ store on iter 0)
        #pragma unroll
        for (int i = 0; i < 4; i++) {
            int idx = tid + i * 128;
            int r = idx >> 3, cseg = idx & 7;
            *(uint4*)(sK + r * FSTR + cseg * 16) =
                *(const uint4*)(K + base + (size_t)(s0 + r) * DMODEL + cseg * 8);
            *(uint4*)(sV + r * FSTR + cseg * 16) =
                *(const uint4*)(V + base + (size_t)(s0 + r) * DMODEL + cseg * 8);
        }
        __syncthreads();
        if (s0 == 0) {
            #pragma unroll
            for (int ks = 0; ks < 4; ks++)
                ldsm4(qf[ks], sqb + (w * 16 + (lane & 15)) * FSTR + ks * 32
                               + ((lane >> 4) << 4));
        }
        // ---- S = Q K^T (fp32 accum) ----
        float sc[8][4] = {};
        #pragma unroll
        for (int ks = 0; ks < 4; ks++) {
            #pragma unroll
            for (int nj = 0; nj < 8; nj++) {
                uint32_t bf[2];
                ldsm2(bf, skb + (nj * 8 + (lane & 7)) * FSTR + ks * 32
                           + (((lane >> 3) & 1) << 4));
                mma16816(sc[nj], qf[ks], bf);
            }
        }
        // ---- scale + mask (source quirk) ----
        float rmax0 = -FLT_MAX, rmax1 = -FLT_MAX;
        #pragma unroll
        for (int nj = 0; nj < 8; nj++) {
            int sg = s0 + nj * 8 + l2;
            #pragma unroll
            for (int q = 0; q < 2; q++) {
                float v0 = sc[nj][q] * 0.125f;
                float v2 = sc[nj][q + 2] * 0.125f;
                if (sg + q > tg0 || v0 == 0.f) v0 = -FLT_MAX;
                if (sg + q > tg1 || v2 == 0.f) v2 = -FLT_MAX;
                sc[nj][q] = v0; sc[nj][q + 2] = v2;
                rmax0 = fmaxf(rmax0, v0); rmax1 = fmaxf(rmax1, v2);
            }
        }
        rmax0 = fmaxf(rmax0, __shfl_xor_sync(0xFFFFFFFFu, rmax0, 1));
        rmax0 = fmaxf(rmax0, __shfl_xor_sync(0xFFFFFFFFu, rmax0, 2));
        rmax1 = fmaxf(rmax1, __shfl_xor_sync(0xFFFFFFFFu, rmax1, 1));
        rmax1 = fmaxf(rmax1, __shfl_xor_sync(0xFFFFFFFFu, rmax1, 2));
        float nm0 = fmaxf(m_run[0], rmax0), nm1 = fmaxf(m_run[1], rmax1);
        float al0 = expf(m_run[0] - nm0), al1 = expf(m_run[1] - nm1);
        m_run[0] = nm0; m_run[1] = nm1;
        float rs0 = 0.f, rs1 = 0.f;
        #pragma unroll
        for (int nj = 0; nj < 8; nj++) {
            #pragma unroll
            for (int q = 0; q < 2; q++) {
                float p0 = (sc[nj][q]     == -FLT_MAX) ? 0.f : expf(sc[nj][q]     - nm0);
                float p2 = (sc[nj][q + 2] == -FLT_MAX) ? 0.f : expf(sc[nj][q + 2] - nm1);
                sc[nj][q] = p0; sc[nj][q + 2] = p2;
                rs0 += p0; rs1 += p2;
            }
        }
        rs0 += __shfl_xor_sync(0xFFFFFFFFu, rs0, 1);
        rs0 += __shfl_xor_sync(0xFFFFFFFFu, rs0, 2);
        rs1 += __shfl_xor_sync(0xFFFFFFFFu, rs1, 1);
        rs1 += __shfl_xor_sync(0xFFFFFFFFu, rs1, 2);
        l_run[0] = l_run[0] * al0 + rs0;
        l_run[1] = l_run[1] * al1 + rs1;
        #pragma unroll
        for (int nj = 0; nj < 8; nj++) {
            o[nj][0] *= al0; o[nj][1] *= al0;
            o[nj][2] *= al1; o[nj][3] *= al1;
        }
        // ---- O += P V ----
        #pragma unroll
        for (int kv = 0; kv < 4; kv++) {
            uint32_t pa[4];
            pa[0] = h2u(__floats2half2_rn(sc[2*kv][0],   sc[2*kv][1]));
            pa[1] = h2u(__floats2half2_rn(sc[2*kv][2],   sc[2*kv][3]));
            pa[2] = h2u(__floats2half2_rn(sc[2*kv+1][0], sc[2*kv+1][1]));
            pa[3] = h2u(__floats2half2_rn(sc[2*kv+1][2], sc[2*kv+1][3]));
            #pragma unroll
            for (int nj = 0; nj < 8; nj++) {
                uint32_t bf[2];
                ldsm2t(bf, svb + (kv * 16 + (lane & 15)) * FSTR + nj * 16);
                mma16816(o[nj], pa, bf);
            }
        }
    }

    float inv0 = 1.f / l_run[0], inv1 = 1.f / l_run[1];
    float* y0 = Y + base + (size_t)tg0 * DMODEL;
    float* y1 = Y + base + (size_t)tg1 * DMODEL;
    #pragma unroll
    for (int nj = 0; nj < 8; nj++) {
        int c = nj * 8 + l2;
        *(float2*)(y0 + c) = make_float2(o[nj][0] * inv0, o[nj][1] * inv0);
        *(float2*)(y1 + c) = make_float2(o[nj][2] * inv1, o[nj][3] * inv1);
    }
}

// ======================= misc kernels ======================================
template<bool DOMAX>
__device__ __forceinline__ float block_reduce(float x) {
    #pragma unroll
    for (int o = 16; o; o >>= 1) {
        float t = __shfl_xor_sync(0xFFFFFFFFu, x, o);
        x = DOMAX ? fmaxf(x, t) : x + t;
    }
    __shared__ float sh[8];
    int w = threadIdx.x >> 5;
    __syncthreads();
    if ((threadIdx.x & 31) == 0) sh[w] = x;
    __syncthreads();
    float r = sh[0];
    #pragma unroll
    for (int i = 1; i < 8; i++) r = DOMAX ? fmaxf(r, sh[i]) : r + sh[i];
    return r;
}

__global__ __launch_bounds__(256) void embed_kernel(const int* __restrict__ x,
                                                    const float* __restrict__ tok,
                                                    const float* __restrict__ pos,
                                                    float* __restrict__ H) {
    int row = blockIdx.x;
    int tid = row % TSEQ;
    size_t tb = (size_t)x[row] * DMODEL, pb = (size_t)tid * DMODEL;
    size_t hb = (size_t)row * DMODEL;
    #pragma unroll
    for (int i = 0; i < 4; i++) {
        int c = threadIdx.x + i * 256;
        H[hb + c] = tok[tb + c] + pos[pb + c];
    }
}

__global__ __launch_bounds__(256) void ln_kernel(const float* __restrict__ X,
                                                 const float* __restrict__ g,
                                                 const float* __restrict__ b,
                                                 __half* __restrict__ O) {
    size_t base = (size_t)blockIdx.x * DMODEL;
    float v[4], s = 0.f, sq = 0.f;
    #pragma unroll
    for (int i = 0; i < 4; i++) {
        v[i] = X[base + threadIdx.x + i * 256];
        s += v[i]; sq += v[i] * v[i];
    }
    s  = block_reduce<false>(s);
    sq = block_reduce<false>(sq);
    float mu = s * (1.f / DMODEL);
    float rstd = rsqrtf(sq * (1.f / DMODEL) - mu * mu + 1e-5f);
    #pragma unroll
    for (int i = 0; i < 4; i++) {
        int c = threadIdx.x + i * 256;
        O[base + c] = __float2half((v[i] - mu) * rstd * g[c] + b[c]);
    }
}

__global__ __launch_bounds__(256) void oproj_kernel(const float* __restrict__ Y,
                                                    const float* __restrict__ Wo,
                                                    const float* __restrict__ bo,
                                                    float* __restrict__ H) {
    int h = blockIdx.y;
    int m0 = blockIdx.x * 64;
    __shared__ float Ys[64][68];
    __shared__ float Ws[64][64];
    int tid = threadIdx.x;
    #pragma unroll
    for (int i = 0; i < 4; i++) {
        int idx = tid + i * 256;
        int r = idx >> 4, c = (idx & 15) * 4;
        float4 yv = *(const float4*)&Y[((size_t)(m0 + r))*DMODEL + h*HDIM + c];
        Ys[c+0][r] = yv.x; Ys[c+1][r] = yv.y; Ys[c+2][r] = yv.z; Ys[c+3][r] = yv.w;
        *(float4*)&Ws[r][c] = *(const float4*)&Wo[((size_t)h*HDIM + r)*HDIM + c];
    }
    __syncthreads();
    int tr = tid >> 4, tc = tid & 15;
    float acc[4][4] = {};
    #pragma unroll
    for (int k = 0; k < 64; k++) {
        float ra[4], rb[4];
        #pragma unroll
        for (int i = 0; i < 4; i++) ra[i] = Ys[k][tr * 4 + i];
        #pragma unroll
        for (int j = 0; j < 4; j++) rb[j] = Ws[k][tc * 4 + j];
        #pragma unroll
        for (int i = 0; i < 4; i++)
            #pragma unroll
            for (int j = 0; j < 4; j++)
                acc[i][j] += ra[i] * rb[j];
    }
    float4 bv = *(const float4*)&bo[h * HDIM + tc * 4];
    #pragma unroll
    for (int i = 0; i < 4; i++) {
        float* hp = &H[((size_t)(m0 + tr*4 + i))*DMODEL + h*HDIM + tc*4];
        float4 r = *(float4*)hp;
        r.x += acc[i][0] + bv.x; r.y += acc[i][1] + bv.y;
        r.z += acc[i][2] + bv.z; r.w += acc[i][3] + bv.w;
        *(float4*)hp = r;
    }
}

__global__ void transpose16(const float* __restrict__ S, __half* __restrict__ D,
                            int R, int C) {
    __shared__ float t[32][33];
    int c0 = blockIdx.x * 32, r0 = blockIdx.y * 32;
    #pragma unroll
    for (int i = 0; i < 4; i++)
        t[threadIdx.y + i*8][threadIdx.x] =
            S[(size_t)(r0 + threadIdx.y + i*8) * C + c0 + threadIdx.x];
    __syncthreads();
    #pragma unroll
    for (int i = 0; i < 4; i++)
        D[(size_t)(c0 + threadIdx.y + i*8) * R + r0 + threadIdx.x] =
            __float2half(t[threadIdx.x][threadIdx.y + i*8]);
}

__global__ void repack_headT(const float* __restrict__ W, __half* __restrict__ D) {
    __shared__ float t[32][33];
    int h = blockIdx.z;
    int k0 = blockIdx.x * 32, d0 = blockIdx.y * 32;
    #pragma unroll
    for (int i = 0; i < 4; i++)
        t[threadIdx.y + i*8][threadIdx.x] =
            W[((size_t)(h*DMODEL + d0 + threadIdx.y + i*8)) * HDIM + k0 + threadIdx.x];
    __syncthreads();
    #pragma unroll
    for (int i = 0; i < 4; i++)
        D[((size_t)(h*HDIM + k0 + threadIdx.y + i*8)) * DMODEL + d0 + threadIdx.x] =
            __float2half(t[threadIdx.x][threadIdx.y + i*8]);
}

__global__ void catbias(const float* a, const float* b, const float* c, float* o) {
    int i = blockIdx.x * 256 + threadIdx.x;
    o[i] = (i < 1024) ? a[i] : (i < 2048) ? b[i - 1024] : c[i - 2048];
}

// ---------------- driver ----------------------------------------------------
extern "C" void kernel_launch(void* const* d_in, const int* in_sizes, int n_in,
                              void* d_out, int out_size) {
    const int*   x    = (const int*)  d_in[0];
    const float* tok  = (const float*)d_in[1];
    const float* pos  = (const float*)d_in[2];
    const float* Wq   = (const float*)d_in[3];
    const float* bq   = (const float*)d_in[4];
    const float* Wk   = (const float*)d_in[5];
    const float* bk   = (const float*)d_in[6];
    const float* Wv   = (const float*)d_in[7];
    const float* bv   = (const float*)d_in[8];
    const float* Wo   = (const float*)d_in[9];
    const float* bo   = (const float*)d_in[10];
    const float* W1   = (const float*)d_in[11];
    const float* b1   = (const float*)d_in[12];
    const float* W2   = (const float*)d_in[13];
    const float* b2   = (const float*)d_in[14];
    const float* ln1g = (const float*)d_in[15];
    const float* ln1b = (const float*)d_in[16];
    const float* ln2g = (const float*)d_in[17];
    const float* ln2b = (const float*)d_in[18];
    const float* lnfg = (const float*)d_in[19];
    const float* lnfb = (const float*)d_in[20];
    const float* Wout = (const float*)d_in[21];
    const float* bout = (const float*)d_in[22];
    float* out = (float*)d_out;

    float *ph, *py, *pbqkv;
    __half *pxn, *pff, *pq, *pk, *pv, *pwqkv, *pw1t, *pw2t, *pwoT;
    cudaGetSymbolAddress((void**)&ph,    g_h);
    cudaGetSymbolAddress((void**)&pxn,   g_xn16);
    cudaGetSymbolAddress((void**)&pq,    g_q16);
    cudaGetSymbolAddress((void**)&pk,    g_k16);
    cudaGetSymbolAddress((void**)&pv,    g_v16);
    cudaGetSymbolAddress((void**)&py,    g_y);
    cudaGetSymbolAddress((void**)&pff,   g_ff16);
    cudaGetSymbolAddress((void**)&pwqkv, g_wqkv);
    cudaGetSymbolAddress((void**)&pbqkv, g_bqkv);
    cudaGetSymbolAddress((void**)&pw1t,  g_w1t);
    cudaGetSymbolAddress((void**)&pw2t,  g_w2t);
    cudaGetSymbolAddress((void**)&pwoT,  g_woT);

    dim3 tb(32, 8);
    repack_headT<<<dim3(2, 32, 16), tb>>>(Wq, pwqkv);
    repack_headT<<<dim3(2, 32, 16), tb>>>(Wk, pwqkv + (size_t)DMODEL*DMODEL);
    repack_headT<<<dim3(2, 32, 16), tb>>>(Wv, pwqkv + (size_t)2*DMODEL*DMODEL);
    catbias<<<12, 256>>>(bq, bk, bv, pbqkv);
    transpose16<<<dim3(FFDIM/32, DMODEL/32), tb>>>(W1, pw1t, DMODEL, FFDIM);
    transpose16<<<dim3(DMODEL/32, FFDIM/32), tb>>>(W2, pw2t, FFDIM, DMODEL);
    transpose16<<<dim3(VOCAB/32, DMODEL/32), tb>>>(Wout, pwoT, DMODEL, VOCAB);

    embed_kernel<<<NTOK, 256>>>(x, tok, pos, ph);

    for (int layer = 0; layer < NLAYER; layer++) {
        ln_kernel<<<NTOK, 256>>>(ph, ln1g, ln1b, pxn);
        tgemm<3><<<dim3(NTOK/BM, 3*DMODEL/BN), 256>>>(
            pxn, pwqkv, pbqkv, nullptr, pq, pk, pv, 3*DMODEL, DMODEL);

        fattn_kernel<<<dim3(TSEQ/64, BATCH*NHEAD), 128>>>(pq, pk, pv, py);
        oproj_kernel<<<dim3(NTOK/64, NHEAD), 256>>>(py, Wo, bo, ph);

        ln_kernel<<<NTOK, 256>>>(ph, ln2g, ln2b, pxn);
        tgemm<1><<<dim3(NTOK/BM, FFDIM/BN), 256>>>(
            pxn, pw1t, b1, nullptr, pff, nullptr, nullptr, FFDIM, DMODEL);
        tgemm<2><<<dim3(NTOK/BM, DMODEL/BN), 256>>>(
            pff, pw2t, b2, ph, nullptr, nullptr, nullptr, DMODEL, FFDIM);
    }

    ln_kernel<<<NTOK, 256>>>(ph, lnfg, lnfb, pxn);
    tgemm<0><<<dim3(NTOK/BM, VOCAB/BN), 256>>>(
        pxn, pwoT, bout, out, nullptr, nullptr, nullptr, VOCAB, DMODEL);
}